// round 16
// baseline (speedup 1.0000x reference)
#include <cuda_runtime.h>

#define LSEQ   2048
#define NBATCH 2
#define NHEADS 16
#define DMODEL 1024
#define BQ     128

#define KSTR 68   // K smem row stride: b-frag pattern conflict-free
#define VSTR 72   // V smem row stride: b-frag pattern conflict-free
#define FSTR 36   // fc smem stride

// Scratch for attention output before the fc GEMM (16.8 MB).
__device__ float g_attn[(size_t)NBATCH * LSEQ * DMODEL];

__device__ __forceinline__ unsigned f2t(float x) {
    unsigned r;
    asm("cvt.rna.tf32.f32 %0, %1;" : "=r"(r) : "f"(x));
    return r;
}

__device__ __forceinline__ void mma8(float* c, const unsigned* a, const unsigned* b) {
    asm volatile(
        "mma.sync.aligned.m16n8k8.row.col.f32.tf32.tf32.f32 "
        "{%0,%1,%2,%3}, {%4,%5,%6,%7}, {%8,%9}, {%0,%1,%2,%3};"
        : "+f"(c[0]), "+f"(c[1]), "+f"(c[2]), "+f"(c[3])
        : "r"(a[0]), "r"(a[1]), "r"(a[2]), "r"(a[3]), "r"(b[0]), "r"(b[1]));
}

// ---------------------------------------------------------------------------
// Kernel 1: flash attention, tf32 tensor cores, register-resident P.
// CTA = (128-query tile, head, batch), 256 threads = 8 warps, warp owns 16 rows.
// Same per-warp code as the measured-good R11 kernel; K/V fill is shared by
// 2x the warps (4 iters/thread instead of 8).
// ---------------------------------------------------------------------------
__global__ __launch_bounds__(256) void attn_kernel(
    const float* __restrict__ Q, const float* __restrict__ K,
    const float* __restrict__ V, const int* __restrict__ mask)
{
    __shared__ unsigned Ks[64 * KSTR];   // K tile (tf32 bits)
    __shared__ unsigned Vs[64 * VSTR];   // V tile (tf32 bits)
    __shared__ int Ms[64];

    const int tid  = threadIdx.x;
    const int w    = tid >> 5;    // 0..7
    const int lane = tid & 31;
    const int gid  = lane >> 2;   // 0..7
    const int tig  = lane & 3;    // 0..3
    const int odd  = tig & 1;
    const int src1 = (lane & 28) | (tig >> 1);
    const int src2 = src1 + 2;

    const int n = blockIdx.z, h = blockIdx.y;
    const int q0 = blockIdx.x * BQ;

    const float* Qg = Q + ((size_t)n * LSEQ) * DMODEL + h * 64;
    const float* Kg = K + ((size_t)n * LSEQ) * DMODEL + h * 64;
    const float* Vg = V + ((size_t)n * LSEQ) * DMODEL + h * 64;
    const int*   Mg = mask + n * LSEQ;

    const int r_lo = 16 * w + gid;       // 0..127
    const int r_hi = r_lo + 8;

    // Q A-fragments in registers: 8 k-steps x 4 regs
    unsigned qa[8][4];
    {
        const float* q0p = Qg + (size_t)(q0 + r_lo) * DMODEL;
        const float* q1p = q0p + 8 * DMODEL;
        #pragma unroll
        for (int s = 0; s < 8; s++) {
            qa[s][0] = f2t(q0p[8 * s + tig]);
            qa[s][1] = f2t(q1p[8 * s + tig]);
            qa[s][2] = f2t(q0p[8 * s + tig + 4]);
            qa[s][3] = f2t(q1p[8 * s + tig + 4]);
        }
    }

    float Oc[8][4];
    #pragma unroll
    for (int j = 0; j < 8; j++)
        #pragma unroll
        for (int r = 0; r < 4; r++) Oc[j][r] = 0.f;

    float l_lo = 0.f, l_hi = 0.f;
    const float scale = 0.03125f;   // 1/sqrt(1024)

    for (int k0 = 0; k0 < LSEQ; k0 += 64) {
        __syncthreads();

        // Load K,V 64x64 tiles (coalesced), convert to tf32 bits.
        // 256 threads: 4 float4 rounds cover 64x64.
        #pragma unroll
        for (int i = 0; i < 4; i++) {
            const int f = tid * 4 + i * 1024;
            const int r = f >> 6, c = f & 63;
            float4 kv = *(const float4*)(Kg + (size_t)(k0 + r) * DMODEL + c);
            Ks[r * KSTR + c + 0] = f2t(kv.x);
            Ks[r * KSTR + c + 1] = f2t(kv.y);
            Ks[r * KSTR + c + 2] = f2t(kv.z);
            Ks[r * KSTR + c + 3] = f2t(kv.w);
            float4 vv = *(const float4*)(Vg + (size_t)(k0 + r) * DMODEL + c);
            Vs[r * VSTR + c + 0] = f2t(vv.x);
            Vs[r * VSTR + c + 1] = f2t(vv.y);
            Vs[r * VSTR + c + 2] = f2t(vv.z);
            Vs[r * VSTR + c + 3] = f2t(vv.w);
        }
        if (tid < 64) Ms[tid] = Mg[k0 + tid];
        __syncthreads();

        // S = Q K^T
        float Sc[8][4];
        #pragma unroll
        for (int j = 0; j < 8; j++)
            #pragma unroll
            for (int r = 0; r < 4; r++) Sc[j][r] = 0.f;

        #pragma unroll
        for (int s = 0; s < 8; s++) {
            #pragma unroll
            for (int j = 0; j < 8; j++) {
                unsigned b[2];
                b[0] = Ks[(8 * j + gid) * KSTR + 8 * s + tig];
                b[1] = Ks[(8 * j + gid) * KSTR + 8 * s + tig + 4];
                mma8(Sc[j], qa[s], b);
            }
        }

        // P = exp(scale * S), masked -> 0 (fixed-max softmax, exact).
        #pragma unroll
        for (int j = 0; j < 8; j++) {
            const int mk0 = Ms[8 * j + 2 * tig];
            const int mk1 = Ms[8 * j + 2 * tig + 1];
            const float p0 = mk0 ? __expf(Sc[j][0] * scale) : 0.f;
            const float p1 = mk1 ? __expf(Sc[j][1] * scale) : 0.f;
            const float p2 = mk0 ? __expf(Sc[j][2] * scale) : 0.f;
            const float p3 = mk1 ? __expf(Sc[j][3] * scale) : 0.f;
            Sc[j][0] = p0; Sc[j][1] = p1; Sc[j][2] = p2; Sc[j][3] = p3;
            l_lo += p0 + p1;
            l_hi += p2 + p3;
        }

        // O += P V : P permuted C->A layout via quad shuffles.
        #pragma unroll
        for (int s = 0; s < 8; s++) {
            const float x0 = __shfl_sync(0xffffffffu, Sc[s][0], src1);
            const float x1 = __shfl_sync(0xffffffffu, Sc[s][1], src1);
            const float x2 = __shfl_sync(0xffffffffu, Sc[s][2], src1);
            const float x3 = __shfl_sync(0xffffffffu, Sc[s][3], src1);
            const float y0 = __shfl_sync(0xffffffffu, Sc[s][0], src2);
            const float y1 = __shfl_sync(0xffffffffu, Sc[s][1], src2);
            const float y2 = __shfl_sync(0xffffffffu, Sc[s][2], src2);
            const float y3 = __shfl_sync(0xffffffffu, Sc[s][3], src2);
            unsigned pa[4];
            pa[0] = f2t(odd ? x1 : x0);
            pa[1] = f2t(odd ? x3 : x2);
            pa[2] = f2t(odd ? y1 : y0);
            pa[3] = f2t(odd ? y3 : y2);
            #pragma unroll
            for (int j = 0; j < 8; j++) {
                unsigned b[2];
                b[0] = Vs[(8 * s + tig) * VSTR + 8 * j + gid];
                b[1] = Vs[(8 * s + tig + 4) * VSTR + 8 * j + gid];
                mma8(Oc[j], pa, b);
            }
        }
    }

    #pragma unroll
    for (int o = 1; o <= 2; o <<= 1) {
        l_lo += __shfl_xor_sync(0xffffffffu, l_lo, o);
        l_hi += __shfl_xor_sync(0xffffffffu, l_hi, o);
    }
    const float inv_lo = 1.f / l_lo;
    const float inv_hi = 1.f / l_hi;

    float* Og = g_attn + ((size_t)n * LSEQ) * DMODEL + h * 64;
    #pragma unroll
    for (int j = 0; j < 8; j++) {
        const int c = 8 * j + 2 * tig;
        float2 v0 = make_float2(Oc[j][0] * inv_lo, Oc[j][1] * inv_lo);
        float2 v1 = make_float2(Oc[j][2] * inv_hi, Oc[j][3] * inv_hi);
        *(float2*)(Og + (size_t)(q0 + r_lo) * DMODEL + c) = v0;
        *(float2*)(Og + (size_t)(q0 + r_hi) * DMODEL + c) = v1;
    }
}

// ---------------------------------------------------------------------------
// Kernel 2: out = g_attn @ fc_w^T + fc_b  (tf32 mma)
// EXACT revert to the R6 measured-best: CTA tile 128x128, 256 threads =
// 8 warps (2 m x 4 n), warp tile 64x32. 256 CTAs, 72.2us measured.
// ---------------------------------------------------------------------------
__global__ __launch_bounds__(256) void fc_kernel(
    const float* __restrict__ W, const float* __restrict__ bias,
    float* __restrict__ out)
{
    __shared__ unsigned As[128 * FSTR];
    __shared__ unsigned Ws[128 * FSTR];

    const int tid  = threadIdx.x;
    const int w    = tid >> 5;
    const int lane = tid & 31;
    const int gid  = lane >> 2;
    const int tig  = lane & 3;
    const int wm = w >> 2, wn = w & 3;

    const int i0 = blockIdx.y * 128;
    const int o0 = blockIdx.x * 128;

    float acc[4][4][4];
    #pragma unroll
    for (int mt = 0; mt < 4; mt++)
        #pragma unroll
        for (int j = 0; j < 4; j++)
            #pragma unroll
            for (int r = 0; r < 4; r++) acc[mt][j][r] = 0.f;

    for (int kt = 0; kt < DMODEL; kt += 32) {
        __syncthreads();
        #pragma unroll
        for (int i = 0; i < 4; i++) {
            const int f = tid * 4 + i * 1024;
            const int r = f >> 5, c = f & 31;
            float4 a = *(const float4*)(g_attn + (size_t)(i0 + r) * DMODEL + kt + c);
            As[r * FSTR + c + 0] = f2t(a.x);
            As[r * FSTR + c + 1] = f2t(a.y);
            As[r * FSTR + c + 2] = f2t(a.z);
            As[r * FSTR + c + 3] = f2t(a.w);
            float4 wv = *(const float4*)(W + (size_t)(o0 + r) * DMODEL + kt + c);
            Ws[r * FSTR + c + 0] = f2t(wv.x);
            Ws[r * FSTR + c + 1] = f2t(wv.y);
            Ws[r * FSTR + c + 2] = f2t(wv.z);
            Ws[r * FSTR + c + 3] = f2t(wv.w);
        }
        __syncthreads();

        #pragma unroll
        for (int ks = 0; ks < 32; ks += 8) {
            unsigned a[4][4], b[4][2];
            #pragma unroll
            for (int mt = 0; mt < 4; mt++) {
                const int r = 64 * wm + 16 * mt;
                a[mt][0] = As[(r + gid) * FSTR + ks + tig];
                a[mt][1] = As[(r + gid + 8) * FSTR + ks + tig];
                a[mt][2] = As[(r + gid) * FSTR + ks + tig + 4];
                a[mt][3] = As[(r + gid + 8) * FSTR + ks + tig + 4];
            }
            #pragma unroll
            for (int j = 0; j < 4; j++) {
                const int o = 32 * wn + 8 * j;
                b[j][0] = Ws[(o + gid) * FSTR + ks + tig];
                b[j][1] = Ws[(o + gid) * FSTR + ks + tig + 4];
            }
            #pragma unroll
            for (int mt = 0; mt < 4; mt++)
                #pragma unroll
                for (int j = 0; j < 4; j++)
                    mma8(acc[mt][j], a[mt], b[j]);
        }
    }

    #pragma unroll
    for (int mt = 0; mt < 4; mt++) {
        const int r_lo = i0 + 64 * wm + 16 * mt + gid;
        const int r_hi = r_lo + 8;
        #pragma unroll
        for (int j = 0; j < 4; j++) {
            const int o = o0 + 32 * wn + 8 * j + 2 * tig;
            const float b0 = bias[o], b1 = bias[o + 1];
            float2 v0 = make_float2(acc[mt][j][0] + b0, acc[mt][j][1] + b1);
            float2 v1 = make_float2(acc[mt][j][2] + b0, acc[mt][j][3] + b1);
            *(float2*)(out + (size_t)r_lo * DMODEL + o) = v0;
            *(float2*)(out + (size_t)r_hi * DMODEL + o) = v1;
        }
    }
}

// ---------------------------------------------------------------------------
extern "C" void kernel_launch(void* const* d_in, const int* in_sizes, int n_in,
                              void* d_out, int out_size) {
    (void)in_sizes; (void)n_in; (void)out_size;
    const float* Q    = (const float*)d_in[0];
    const float* K    = (const float*)d_in[1];
    const float* V    = (const float*)d_in[2];
    const int*   mask = (const int*)d_in[3];
    const float* W    = (const float*)d_in[4];
    const float* b    = (const float*)d_in[5];
    float* out = (float*)d_out;

    attn_kernel<<<dim3(LSEQ / BQ, NHEADS, NBATCH), 256>>>(Q, K, V, mask);
    fc_kernel<<<dim3(DMODEL / 128, (NBATCH * LSEQ) / 128), 256>>>(W, b, out);
}